// round 16
// baseline (speedup 1.0000x reference)
#include <cuda_runtime.h>
#include <cuda_fp16.h>
#include <math.h>
#include <cstdint>

#define BATCH 8
#define HH_ 128
#define P_TOT (BATCH*HH_*HH_)   // 131072
#define C_DIM 64
#define IN_CH 192
#define HID_CH 384

// ---------------- scratch ----------------------------------------------------
__device__ __align__(16) __half g_high_h[(size_t)P_TOT * IN_CH];
__device__ __align__(16) __half g_hid_h[(size_t)P_TOT * HID_CH];
__device__ __align__(16) __half g_act_h[(size_t)P_TOT * HID_CH];
__device__ __align__(16) __half g_w1h[HID_CH * IN_CH];
__device__ __align__(16) __half g_w2h[IN_CH * HID_CH];
__device__ __align__(16) float  g_bias1[HID_CH];
__device__ __align__(16) float  g_part[2048 * 384];
__device__ __align__(16) float  g_bns[IN_CH];
__device__ __align__(16) float  g_bnb[IN_CH];

// ---------------- helpers ----------------------------------------------------
__device__ __forceinline__ uint32_t smem_u32(const void* p) {
    uint32_t a;
    asm("{ .reg .u64 tmp; cvta.to.shared.u64 tmp, %1; cvt.u32.u64 %0, tmp; }"
        : "=r"(a) : "l"(p));
    return a;
}
#define CP_ASYNC16(dst, src) \
    asm volatile("cp.async.cg.shared.global [%0], [%1], 16;" :: "r"(dst), "l"(src))
#define CP_COMMIT()  asm volatile("cp.async.commit_group;" ::: "memory")
#define CP_WAIT1()   asm volatile("cp.async.wait_group 1;" ::: "memory")

__device__ __forceinline__ void ldsm_x4(uint32_t& r0, uint32_t& r1,
                                        uint32_t& r2, uint32_t& r3, uint32_t addr) {
    asm volatile("ldmatrix.sync.aligned.m8n8.x4.shared.b16 {%0,%1,%2,%3}, [%4];"
        : "=r"(r0), "=r"(r1), "=r"(r2), "=r"(r3) : "r"(addr));
}

__device__ __forceinline__ void mma_f16(float* c, const uint32_t* a, const uint32_t* b) {
    asm volatile(
        "mma.sync.aligned.m16n8k16.row.col.f32.f16.f16.f32 "
        "{%0,%1,%2,%3}, {%4,%5,%6,%7}, {%8,%9}, {%0,%1,%2,%3};"
        : "+f"(c[0]), "+f"(c[1]), "+f"(c[2]), "+f"(c[3])
        : "r"(a[0]), "r"(a[1]), "r"(a[2]), "r"(a[3]), "r"(b[0]), "r"(b[1]));
}

// ---------------- Kernel 1: DWT + BN partials; LL straight into out ----------
// grid (1024, 2): y selects j-half -> 16 serial iters/thread, 2048 blocks.
__global__ void k_dwt(const float* __restrict__ x, float* __restrict__ out) {
    int bi = blockIdx.x;
    int jh = blockIdx.y;
    int b = bi >> 7, i = bi & 127;
    int t = threadIdx.x;
    int c = t & 63, jq = t >> 6;

    float s0=0,s1=0,s2=0,s3=0, q0=0,q1=0,q2=0,q3=0;
    const float* xr0 = x + (size_t)(b*256 + 2*i) * 256 * 64;
    const float* xr1 = xr0 + 256*64;
    float* orow0 = out + (size_t)(b*256 + 2*i) * 256 * 64;
    const bool isHigh = (c >= 16);
    const int f = 4*c;
    const int j0 = jh * 64;

    for (int j = j0 + jq; j < j0 + 64; j += 4) {
        int col = 2*j*64 + c;
        float a  = xr0[col],  bb = xr0[col+64];
        float cc = xr1[col],  dd = xr1[col+64];
        float ll = 0.5f*(a+bb+cc+dd);
        float lh = 0.5f*(a-bb+cc-dd);
        float hl = 0.5f*(a+bb-cc-dd);
        float hh = 0.5f*(a-bb-cc+dd);
        size_t p = (size_t)bi*128 + j;
        if (!isHigh) {
            *(float4*)(orow0 + 2*j*64 + f) = make_float4(ll, lh, hl, hh);
        } else {
            __half2 h0 = __floats2half2_rn(ll, lh);
            __half2 h1 = __floats2half2_rn(hl, hh);
            uint2 u;
            u.x = *(uint32_t*)&h0;
            u.y = *(uint32_t*)&h1;
            *(uint2*)(g_high_h + p*192 + (f - 64)) = u;
            s0 += ll; s1 += lh; s2 += hl; s3 += hh;
            q0 += ll*ll; q1 += lh*lh; q2 += hl*hl; q3 += hh*hh;
        }
    }

    __shared__ float red[256][8];
    red[t][0]=s0; red[t][1]=s1; red[t][2]=s2; red[t][3]=s3;
    red[t][4]=q0; red[t][5]=q1; red[t][6]=q2; red[t][7]=q3;
    __syncthreads();
    if (t >= 16 && t < 64) {
        int prow = bi*2 + jh;
        #pragma unroll
        for (int k = 0; k < 4; k++) {
            float sv = red[t][k]   + red[64+t][k]   + red[128+t][k]   + red[192+t][k];
            float qv = red[t][4+k] + red[64+t][4+k] + red[128+t][4+k] + red[192+t][4+k];
            int m = 4*(t-16) + k;
            g_part[(size_t)prow*384 + m]       = sv;
            g_part[(size_t)prow*384 + 192 + m] = qv;
        }
    }
}

// ---------------- Kernel 2: BN finalize --------------------------------------
__global__ void k_bnfin(const float* __restrict__ gamma,
                        const float* __restrict__ beta) {
    int t = threadIdx.x;  // 384
    float s = 0.f;
    for (int r = 0; r < 2048; r++) s += g_part[(size_t)r*384 + t];
    __shared__ float sm[384];
    sm[t] = s;
    __syncthreads();
    if (t < 192) {
        const float N = (float)P_TOT;
        float mean = sm[t] / N;
        float var  = sm[t+192] / N - mean*mean;
        float sc   = gamma[t] * rsqrtf(var + 1e-5f);
        g_bns[t] = sc;
        g_bnb[t] = beta[t] - mean * sc;
    }
}

// ---------------- Kernel 3: weight prep (BN fold + half convert) -------------
__global__ void k_wprep(const float* __restrict__ w_in,
                        const float* __restrict__ w_out) {
    int b = blockIdx.x, t = threadIdx.x;   // 192 threads
    if (b < 384) {
        float wv = w_in[b*192 + t];
        g_w1h[b*192 + t] = __float2half_rn(wv * g_bns[t]);
        float p = wv * g_bnb[t];
        #pragma unroll
        for (int o = 16; o; o >>= 1) p += __shfl_down_sync(0xffffffffu, p, o);
        __shared__ float sw[6];
        if ((t & 31) == 0) sw[t >> 5] = p;
        __syncthreads();
        if (t == 0)
            g_bias1[b] = sw[0]+sw[1]+sw[2]+sw[3]+sw[4]+sw[5];
    } else {
        int i = (b - 384)*192 + t;
        g_w2h[i] = __float2half_rn(w_out[i]);
    }
}

// ---------------- fp16 MMA GEMM: BM=128, BN=192, BK=16, 512 thr, 3-stage -----
// (R14 config — best measured)
template<int LDK>
__device__ __forceinline__ void gemm_prefetch(uint32_t smem_base,
                                              const __half* __restrict__ A,
                                              const __half* __restrict__ W,
                                              size_t pbase, int t, int ic, int stage) {
    constexpr int AW  = 128 * 12;
    constexpr int STG = AW + 192 * 12;
    const int kc = ic * 16;
    if (t < 256) {                      // A: 128 rows x 2 segs
        int row = t >> 1, seg = t & 1;
        uint32_t dst = smem_base + (uint32_t)(stage*STG + row*12 + seg*4) * 4;
        CP_ASYNC16(dst, A + (pbase + row)*LDK + kc + seg*8);
    }
    if (t >= 128) {                     // W: 192 rows x 2 segs = 384 units
        int f = t - 128;
        int n = f >> 1, seg = f & 1;
        uint32_t dst = smem_base + (uint32_t)(stage*STG + AW + n*12 + seg*4) * 4;
        CP_ASYNC16(dst, W + (size_t)n*LDK + kc + seg*8);
    }
}

// MODE 0: +bias, store half to out_h.  MODE 1: residual + fused iwt scatter.
template<int LDK, int MODE>
__device__ __forceinline__ void gemm_core(const __half* __restrict__ A,
                                          const __half* __restrict__ W,
                                          int obase,
                                          __half* __restrict__ out_h,
                                          float* __restrict__ out_f,
                                          const float* __restrict__ res_scale) {
    constexpr int NT  = 6;
    constexpr int NC  = LDK / 16;
    constexpr int AW  = 128 * 12;
    constexpr int STG = AW + 192 * 12;

    extern __shared__ uint32_t smw[];
    const uint32_t smem_base = smem_u32(smw);

    const int t = threadIdx.x;
    const int lane = t & 31, wp = t >> 5;
    const int g = lane >> 2, qi = lane & 3;
    const int warpM = (wp & 3) * 32;
    const int warpN = (wp >> 2) * 48;
    const size_t pbase = (size_t)blockIdx.y * 128;

    uint32_t aAddr[2];
    #pragma unroll
    for (int mt = 0; mt < 2; mt++) {
        int row  = warpM + mt*16 + (lane & 7) + ((lane >> 3) & 1) * 8;
        int word = (lane & 16) ? 4 : 0;
        aAddr[mt] = smem_base + (uint32_t)(row*12 + word) * 4;
    }
    uint32_t bAddr[3];
    #pragma unroll
    for (int ntp = 0; ntp < 3; ntp++) {
        int row  = warpN + ntp*16 + ((lane >> 4) & 1) * 8 + (lane & 7);
        int word = ((lane >> 3) & 1) * 4;
        bAddr[ntp] = smem_base + (uint32_t)(AW + row*12 + word) * 4;
    }

    float c[2][NT][4];
    #pragma unroll
    for (int mt = 0; mt < 2; mt++)
        #pragma unroll
        for (int nt = 0; nt < NT; nt++)
            #pragma unroll
            for (int q = 0; q < 4; q++) c[mt][nt][q] = 0.f;

    gemm_prefetch<LDK>(smem_base, A, W, pbase, t, 0, 0);
    CP_COMMIT();
    gemm_prefetch<LDK>(smem_base, A, W, pbase, t, 1, 1);
    CP_COMMIT();

    int st = 0;
    for (int ic = 0; ic < NC; ic++) {
        CP_WAIT1();
        __syncthreads();

        const uint32_t soff = (uint32_t)(st * STG * 4);
        uint32_t a[2][4], bb[3][4];
        ldsm_x4(a[0][0], a[0][1], a[0][2], a[0][3], aAddr[0] + soff);
        ldsm_x4(a[1][0], a[1][1], a[1][2], a[1][3], aAddr[1] + soff);
        ldsm_x4(bb[0][0], bb[0][1], bb[0][2], bb[0][3], bAddr[0] + soff);
        ldsm_x4(bb[1][0], bb[1][1], bb[1][2], bb[1][3], bAddr[1] + soff);
        ldsm_x4(bb[2][0], bb[2][1], bb[2][2], bb[2][3], bAddr[2] + soff);

        if (ic + 2 < NC) {
            int ns = st + 2; if (ns >= 3) ns -= 3;
            gemm_prefetch<LDK>(smem_base, A, W, pbase, t, ic+2, ns);
        }
        CP_COMMIT();   // uniform: one group per iteration (may be empty)

        #pragma unroll
        for (int ntp = 0; ntp < 3; ntp++) {
            mma_f16(c[0][2*ntp],   a[0], &bb[ntp][0]);
            mma_f16(c[1][2*ntp],   a[1], &bb[ntp][0]);
            mma_f16(c[0][2*ntp+1], a[0], &bb[ntp][2]);
            mma_f16(c[1][2*ntp+1], a[1], &bb[ntp][2]);
        }
        if (++st == 3) st = 0;
    }

    if (MODE == 0) {
        #pragma unroll
        for (int mt = 0; mt < 2; mt++) {
            #pragma unroll
            for (int hi = 0; hi < 2; hi++) {
                int row = warpM + mt*16 + g + hi*8;
                __half* orow = out_h + (pbase + row) * 384 + obase;
                #pragma unroll
                for (int nt = 0; nt < NT; nt++) {
                    int col = warpN + nt*8 + qi*2;
                    float2 bv = *(const float2*)(g_bias1 + obase + col);
                    __half2 hv = __floats2half2_rn(c[mt][nt][hi*2]   + bv.x,
                                                   c[mt][nt][hi*2+1] + bv.y);
                    *(__half2*)(orow + col) = hv;
                }
            }
        }
    } else {
        const float rs = __ldg(res_scale);
        #pragma unroll
        for (int mt = 0; mt < 2; mt++) {
            #pragma unroll
            for (int hi = 0; hi < 2; hi++) {
                int row = warpM + mt*16 + g + hi*8;
                size_t p = pbase + row;
                int bi = (int)(p >> 7);
                int j  = (int)(p & 127);
                int b  = bi >> 7, i = bi & 127;
                const __half* hrow = g_high_h + p*192;
                size_t base = ((size_t)(b*256 + 2*i) * 256 + 2*j) * 64;
                #pragma unroll
                for (int nt = 0; nt < NT; nt++) {
                    int col = warpN + nt*8 + qi*2;
                    int gq = col >> 6, cc = col & 63;
                    float2 hv = __half22float2(*(const __half2*)(hrow + col));
                    float v0 = fmaf(rs, c[mt][nt][hi*2 + 0], hv.x);
                    float v1 = fmaf(rs, c[mt][nt][hi*2 + 1], hv.y);
                    size_t addr = base + cc
                                + ((gq >= 1) ? (size_t)256*64 : 0)
                                + ((gq != 1) ? 64 : 0);
                    *(float2*)(out_f + addr) = make_float2(v0, v1);
                }
            }
        }
    }
}

// grid (2, 1024): x = n-block (adjacent CTAs share the A tile via L2), y = p-block
__global__ void __launch_bounds__(512) k_gemm1() {
    int obase = blockIdx.x * 192;
    gemm_core<192, 0>(g_high_h, g_w1h + (size_t)obase*192, obase,
                      g_hid_h, nullptr, nullptr);
}
// grid (1, 1024)
__global__ void __launch_bounds__(512) k_gemm2(float* __restrict__ out,
                                               const float* __restrict__ rs) {
    gemm_core<384, 1>(g_act_h, g_w2h, 0, nullptr, out, rs);
}

// ---------------- Kernel 4: depthwise 3x3 + exact GELU (half in/out) ---------
// grid (1024, 2), block (96, 4): 16 cols/thread -> halved serial chain, 2x blocks
__global__ void k_dw(const float* __restrict__ w_dw) {
    int bi = blockIdx.x;
    int i  = bi & 127;
    int ch = threadIdx.x * 4;
    int jb = (blockIdx.y * 4 + threadIdx.y) * 16;

    float w[3][3][4];
    #pragma unroll
    for (int r = 0; r < 3; r++)
        #pragma unroll
        for (int cc = 0; cc < 3; cc++)
            #pragma unroll
            for (int q = 0; q < 4; q++)
                w[r][cc][q] = w_dw[(ch+q)*9 + r*3 + cc];

    const __half* r1 = g_hid_h + (size_t)bi*49152 + ch;
    const __half* r0 = r1 - 49152;
    const __half* r2 = r1 + 49152;
    const bool up = (i > 0), dn = (i < 127);

    float L[3][4], M[3][4], R[3][4];

#define DW_CVT(dst, u) do {                                                   \
    __half2 _h0 = *(__half2*)&(u).x, _h1 = *(__half2*)&(u).y;                 \
    float2 _f0 = __half22float2(_h0), _f1 = __half22float2(_h1);              \
    dst[0] = _f0.x; dst[1] = _f0.y; dst[2] = _f1.x; dst[3] = _f1.y;           \
} while (0)

#define DW_LOADCOL(dst, jj) do {                                              \
    if ((jj) >= 0 && (jj) < 128) {                                            \
        uint2 _zz = make_uint2(0, 0);                                         \
        uint2 _ua = up ? *(const uint2*)(r0 + (size_t)(jj)*384) : _zz;        \
        uint2 _ub = *(const uint2*)(r1 + (size_t)(jj)*384);                   \
        uint2 _uc = dn ? *(const uint2*)(r2 + (size_t)(jj)*384) : _zz;        \
        DW_CVT(dst[0], _ua); DW_CVT(dst[1], _ub); DW_CVT(dst[2], _uc);        \
    } else {                                                                  \
        _Pragma("unroll") for (int _r = 0; _r < 3; _r++)                      \
            _Pragma("unroll") for (int _q = 0; _q < 4; _q++) dst[_r][_q] = 0.f; \
    } } while (0)

    DW_LOADCOL(L, jb-1);
    DW_LOADCOL(M, jb);

    __half* obase = g_act_h + (size_t)bi*128*384 + ch;
    for (int j = jb; j < jb + 16; j++) {
        DW_LOADCOL(R, j+1);
        float s[4];
        #pragma unroll
        for (int q = 0; q < 4; q++) {
            float v = L[0][q]*w[0][0][q] + M[0][q]*w[0][1][q] + R[0][q]*w[0][2][q]
                    + L[1][q]*w[1][0][q] + M[1][q]*w[1][1][q] + R[1][q]*w[1][2][q]
                    + L[2][q]*w[2][0][q] + M[2][q]*w[2][1][q] + R[2][q]*w[2][2][q];
            s[q] = 0.5f * v * (1.f + erff(v * 0.70710678118654752f));
        }
        __half2 h0 = __floats2half2_rn(s[0], s[1]);
        __half2 h1 = __floats2half2_rn(s[2], s[3]);
        uint2 u;
        u.x = *(uint32_t*)&h0;
        u.y = *(uint32_t*)&h1;
        *(uint2*)(obase + (size_t)j*384) = u;
        #pragma unroll
        for (int r = 0; r < 3; r++)
            #pragma unroll
            for (int q = 0; q < 4; q++) { L[r][q] = M[r][q]; M[r][q] = R[r][q]; }
    }
#undef DW_LOADCOL
#undef DW_CVT
}

// ---------------- launch ------------------------------------------------------
extern "C" void kernel_launch(void* const* d_in, const int* in_sizes, int n_in,
                              void* d_out, int out_size) {
    const float* x     = (const float*)d_in[0];
    const float* gamma = (const float*)d_in[1];
    const float* beta  = (const float*)d_in[2];
    const float* w_in  = (const float*)d_in[3];
    const float* w_dw  = (const float*)d_in[4];
    const float* w_out = (const float*)d_in[5];
    const float* rs    = (const float*)d_in[6];
    float* out = (float*)d_out;

    const int SMG = 3 * (128*12 + 192*12) * 4;   // 46080 B (< 48K default)

    k_dwt  <<<dim3(1024, 2), 256>>>(x, out);
    k_bnfin<<<1,    384>>>(gamma, beta);
    k_wprep<<<768,  192>>>(w_in, w_out);
    k_gemm1<<<dim3(2, 1024), 512, SMG>>>();
    k_dw   <<<dim3(1024, 2), dim3(96, 4)>>>(w_dw);
    k_gemm2<<<dim3(1, 1024), 512, SMG>>>(out, rs);
}

// round 17
// speedup vs baseline: 1.1347x; 1.1347x over previous
#include <cuda_runtime.h>
#include <cuda_fp16.h>
#include <math.h>
#include <cstdint>

#define BATCH 8
#define HH_ 128
#define P_TOT (BATCH*HH_*HH_)   // 131072
#define C_DIM 64
#define IN_CH 192
#define HID_CH 384

// ---------------- scratch ----------------------------------------------------
__device__ __align__(16) __half g_high_h[(size_t)P_TOT * IN_CH];
__device__ __align__(16) __half g_hid_h[(size_t)P_TOT * HID_CH];
__device__ __align__(16) __half g_act_h[(size_t)P_TOT * HID_CH];
__device__ __align__(16) __half g_w1h[HID_CH * IN_CH];
__device__ __align__(16) __half g_w2h[IN_CH * HID_CH];
__device__ __align__(16) float  g_bias1[HID_CH];
__device__ __align__(16) float  g_part[1024 * 384];
__device__ __align__(16) float  g_part2[64 * 384];
__device__ __align__(16) float  g_bns[IN_CH];
__device__ __align__(16) float  g_bnb[IN_CH];

// ---------------- helpers ----------------------------------------------------
__device__ __forceinline__ uint32_t smem_u32(const void* p) {
    uint32_t a;
    asm("{ .reg .u64 tmp; cvta.to.shared.u64 tmp, %1; cvt.u32.u64 %0, tmp; }"
        : "=r"(a) : "l"(p));
    return a;
}
#define CP_ASYNC16(dst, src) \
    asm volatile("cp.async.cg.shared.global [%0], [%1], 16;" :: "r"(dst), "l"(src))
#define CP_COMMIT()  asm volatile("cp.async.commit_group;" ::: "memory")
#define CP_WAIT1()   asm volatile("cp.async.wait_group 1;" ::: "memory")

__device__ __forceinline__ void ldsm_x4(uint32_t& r0, uint32_t& r1,
                                        uint32_t& r2, uint32_t& r3, uint32_t addr) {
    asm volatile("ldmatrix.sync.aligned.m8n8.x4.shared.b16 {%0,%1,%2,%3}, [%4];"
        : "=r"(r0), "=r"(r1), "=r"(r2), "=r"(r3) : "r"(addr));
}

__device__ __forceinline__ void mma_f16(float* c, const uint32_t* a, const uint32_t* b) {
    asm volatile(
        "mma.sync.aligned.m16n8k16.row.col.f32.f16.f16.f32 "
        "{%0,%1,%2,%3}, {%4,%5,%6,%7}, {%8,%9}, {%0,%1,%2,%3};"
        : "+f"(c[0]), "+f"(c[1]), "+f"(c[2]), "+f"(c[3])
        : "r"(a[0]), "r"(a[1]), "r"(a[2]), "r"(a[3]), "r"(b[0]), "r"(b[1]));
}

// ---------------- Kernel 1: DWT + BN partials; LL straight into out ----------
__global__ void k_dwt(const float* __restrict__ x, float* __restrict__ out) {
    int bi = blockIdx.x;
    int b = bi >> 7, i = bi & 127;
    int t = threadIdx.x;
    int c = t & 63, jq = t >> 6;

    float s0=0,s1=0,s2=0,s3=0, q0=0,q1=0,q2=0,q3=0;
    const float* xr0 = x + (size_t)(b*256 + 2*i) * 256 * 64;
    const float* xr1 = xr0 + 256*64;
    float* orow0 = out + (size_t)(b*256 + 2*i) * 256 * 64;
    const bool isHigh = (c >= 16);
    const int f = 4*c;

    for (int j = jq; j < 128; j += 4) {
        int col = 2*j*64 + c;
        float a  = xr0[col],  bb = xr0[col+64];
        float cc = xr1[col],  dd = xr1[col+64];
        float ll = 0.5f*(a+bb+cc+dd);
        float lh = 0.5f*(a-bb+cc-dd);
        float hl = 0.5f*(a+bb-cc-dd);
        float hh = 0.5f*(a-bb-cc+dd);
        size_t p = (size_t)bi*128 + j;
        if (!isHigh) {
            *(float4*)(orow0 + 2*j*64 + f) = make_float4(ll, lh, hl, hh);
        } else {
            __half2 h0 = __floats2half2_rn(ll, lh);
            __half2 h1 = __floats2half2_rn(hl, hh);
            uint2 u;
            u.x = *(uint32_t*)&h0;
            u.y = *(uint32_t*)&h1;
            *(uint2*)(g_high_h + p*192 + (f - 64)) = u;
            s0 += ll; s1 += lh; s2 += hl; s3 += hh;
            q0 += ll*ll; q1 += lh*lh; q2 += hl*hl; q3 += hh*hh;
        }
    }

    __shared__ float red[256][8];
    red[t][0]=s0; red[t][1]=s1; red[t][2]=s2; red[t][3]=s3;
    red[t][4]=q0; red[t][5]=q1; red[t][6]=q2; red[t][7]=q3;
    __syncthreads();
    if (t >= 16 && t < 64) {
        #pragma unroll
        for (int k = 0; k < 4; k++) {
            float sv = red[t][k]   + red[64+t][k]   + red[128+t][k]   + red[192+t][k];
            float qv = red[t][4+k] + red[64+t][4+k] + red[128+t][4+k] + red[192+t][4+k];
            int m = 4*(t-16) + k;
            g_part[(size_t)bi*384 + m]       = sv;
            g_part[(size_t)bi*384 + 192 + m] = qv;
        }
    }
}

// ---------------- Kernel 2a: BN partial reduce (64 blocks x 16 rows) ---------
__global__ void k_bnfin1() {
    int b = blockIdx.x;      // 64
    int t = threadIdx.x;     // 384
    float s = 0.f;
    #pragma unroll 4
    for (int r = b*16; r < b*16 + 16; r++) s += g_part[(size_t)r*384 + t];
    g_part2[(size_t)b*384 + t] = s;
}

// ---------------- Kernel 2b: BN finalize (sums 64 rows) ----------------------
__global__ void k_bnfin2(const float* __restrict__ gamma,
                         const float* __restrict__ beta) {
    int t = threadIdx.x;  // 384
    float s = 0.f;
    #pragma unroll 4
    for (int r = 0; r < 64; r++) s += g_part2[(size_t)r*384 + t];
    __shared__ float sm[384];
    sm[t] = s;
    __syncthreads();
    if (t < 192) {
        const float N = (float)P_TOT;
        float mean = sm[t] / N;
        float var  = sm[t+192] / N - mean*mean;
        float sc   = gamma[t] * rsqrtf(var + 1e-5f);
        g_bns[t] = sc;
        g_bnb[t] = beta[t] - mean * sc;
    }
}

// ---------------- Kernel 3: weight prep (BN fold + half convert) -------------
__global__ void k_wprep(const float* __restrict__ w_in,
                        const float* __restrict__ w_out) {
    int b = blockIdx.x, t = threadIdx.x;   // 192 threads
    if (b < 384) {
        float wv = w_in[b*192 + t];
        g_w1h[b*192 + t] = __float2half_rn(wv * g_bns[t]);
        float p = wv * g_bnb[t];
        #pragma unroll
        for (int o = 16; o; o >>= 1) p += __shfl_down_sync(0xffffffffu, p, o);
        __shared__ float sw[6];
        if ((t & 31) == 0) sw[t >> 5] = p;
        __syncthreads();
        if (t == 0)
            g_bias1[b] = sw[0]+sw[1]+sw[2]+sw[3]+sw[4]+sw[5];
    } else {
        int i = (b - 384)*192 + t;
        g_w2h[i] = __float2half_rn(w_out[i]);
    }
}

// ---------------- fp16 MMA GEMM: BM=128, BN=192, BK=16, 512 thr, 3-stage -----
template<int LDK>
__device__ __forceinline__ void gemm_prefetch(uint32_t smem_base,
                                              const __half* __restrict__ A,
                                              const __half* __restrict__ W,
                                              size_t pbase, int t, int ic, int stage) {
    constexpr int AW  = 128 * 12;
    constexpr int STG = AW + 192 * 12;
    const int kc = ic * 16;
    if (t < 256) {                      // A: 128 rows x 2 segs
        int row = t >> 1, seg = t & 1;
        uint32_t dst = smem_base + (uint32_t)(stage*STG + row*12 + seg*4) * 4;
        CP_ASYNC16(dst, A + (pbase + row)*LDK + kc + seg*8);
    }
    if (t >= 128) {                     // W: 192 rows x 2 segs = 384 units
        int f = t - 128;
        int n = f >> 1, seg = f & 1;
        uint32_t dst = smem_base + (uint32_t)(stage*STG + AW + n*12 + seg*4) * 4;
        CP_ASYNC16(dst, W + (size_t)n*LDK + kc + seg*8);
    }
}

// MODE 0: +bias, store half to out_h.  MODE 1: residual + fused iwt scatter.
template<int LDK, int MODE>
__device__ __forceinline__ void gemm_core(const __half* __restrict__ A,
                                          const __half* __restrict__ W,
                                          int obase,
                                          __half* __restrict__ out_h,
                                          float* __restrict__ out_f,
                                          const float* __restrict__ res_scale) {
    constexpr int NT  = 6;
    constexpr int NC  = LDK / 16;
    constexpr int AW  = 128 * 12;
    constexpr int STG = AW + 192 * 12;

    extern __shared__ uint32_t smw[];
    const uint32_t smem_base = smem_u32(smw);

    const int t = threadIdx.x;
    const int lane = t & 31, wp = t >> 5;
    const int g = lane >> 2, qi = lane & 3;
    const int warpM = (wp & 3) * 32;
    const int warpN = (wp >> 2) * 48;
    const size_t pbase = (size_t)blockIdx.y * 128;

    uint32_t aAddr[2];
    #pragma unroll
    for (int mt = 0; mt < 2; mt++) {
        int row  = warpM + mt*16 + (lane & 7) + ((lane >> 3) & 1) * 8;
        int word = (lane & 16) ? 4 : 0;
        aAddr[mt] = smem_base + (uint32_t)(row*12 + word) * 4;
    }
    uint32_t bAddr[3];
    #pragma unroll
    for (int ntp = 0; ntp < 3; ntp++) {
        int row  = warpN + ntp*16 + ((lane >> 4) & 1) * 8 + (lane & 7);
        int word = ((lane >> 3) & 1) * 4;
        bAddr[ntp] = smem_base + (uint32_t)(AW + row*12 + word) * 4;
    }

    float c[2][NT][4];
    #pragma unroll
    for (int mt = 0; mt < 2; mt++)
        #pragma unroll
        for (int nt = 0; nt < NT; nt++)
            #pragma unroll
            for (int q = 0; q < 4; q++) c[mt][nt][q] = 0.f;

    gemm_prefetch<LDK>(smem_base, A, W, pbase, t, 0, 0);
    CP_COMMIT();
    gemm_prefetch<LDK>(smem_base, A, W, pbase, t, 1, 1);
    CP_COMMIT();

    int st = 0;
    for (int ic = 0; ic < NC; ic++) {
        CP_WAIT1();
        __syncthreads();

        const uint32_t soff = (uint32_t)(st * STG * 4);
        uint32_t a[2][4], bb[3][4];
        ldsm_x4(a[0][0], a[0][1], a[0][2], a[0][3], aAddr[0] + soff);
        ldsm_x4(a[1][0], a[1][1], a[1][2], a[1][3], aAddr[1] + soff);
        ldsm_x4(bb[0][0], bb[0][1], bb[0][2], bb[0][3], bAddr[0] + soff);
        ldsm_x4(bb[1][0], bb[1][1], bb[1][2], bb[1][3], bAddr[1] + soff);
        ldsm_x4(bb[2][0], bb[2][1], bb[2][2], bb[2][3], bAddr[2] + soff);

        if (ic + 2 < NC) {
            int ns = st + 2; if (ns >= 3) ns -= 3;
            gemm_prefetch<LDK>(smem_base, A, W, pbase, t, ic+2, ns);
        }
        CP_COMMIT();   // uniform: one group per iteration (may be empty)

        #pragma unroll
        for (int ntp = 0; ntp < 3; ntp++) {
            mma_f16(c[0][2*ntp],   a[0], &bb[ntp][0]);
            mma_f16(c[1][2*ntp],   a[1], &bb[ntp][0]);
            mma_f16(c[0][2*ntp+1], a[0], &bb[ntp][2]);
            mma_f16(c[1][2*ntp+1], a[1], &bb[ntp][2]);
        }
        if (++st == 3) st = 0;
    }

    if (MODE == 0) {
        #pragma unroll
        for (int mt = 0; mt < 2; mt++) {
            #pragma unroll
            for (int hi = 0; hi < 2; hi++) {
                int row = warpM + mt*16 + g + hi*8;
                __half* orow = out_h + (pbase + row) * 384 + obase;
                #pragma unroll
                for (int nt = 0; nt < NT; nt++) {
                    int col = warpN + nt*8 + qi*2;
                    float2 bv = *(const float2*)(g_bias1 + obase + col);
                    __half2 hv = __floats2half2_rn(c[mt][nt][hi*2]   + bv.x,
                                                   c[mt][nt][hi*2+1] + bv.y);
                    *(__half2*)(orow + col) = hv;
                }
            }
        }
    } else {
        const float rs = __ldg(res_scale);
        #pragma unroll
        for (int mt = 0; mt < 2; mt++) {
            #pragma unroll
            for (int hi = 0; hi < 2; hi++) {
                int row = warpM + mt*16 + g + hi*8;
                size_t p = pbase + row;
                int bi = (int)(p >> 7);
                int j  = (int)(p & 127);
                int b  = bi >> 7, i = bi & 127;
                const __half* hrow = g_high_h + p*192;
                size_t base = ((size_t)(b*256 + 2*i) * 256 + 2*j) * 64;
                #pragma unroll
                for (int nt = 0; nt < NT; nt++) {
                    int col = warpN + nt*8 + qi*2;
                    int gq = col >> 6, cc = col & 63;
                    float2 hv = __half22float2(*(const __half2*)(hrow + col));
                    float v0 = fmaf(rs, c[mt][nt][hi*2 + 0], hv.x);
                    float v1 = fmaf(rs, c[mt][nt][hi*2 + 1], hv.y);
                    size_t addr = base + cc
                                + ((gq >= 1) ? (size_t)256*64 : 0)
                                + ((gq != 1) ? 64 : 0);
                    *(float2*)(out_f + addr) = make_float2(v0, v1);
                }
            }
        }
    }
}

// grid (2, 1024): x = n-block (adjacent CTAs share the A tile via L2), y = p-block
__global__ void __launch_bounds__(512) k_gemm1() {
    int obase = blockIdx.x * 192;
    gemm_core<192, 0>(g_high_h, g_w1h + (size_t)obase*192, obase,
                      g_hid_h, nullptr, nullptr);
}
// grid (1, 1024)
__global__ void __launch_bounds__(512) k_gemm2(float* __restrict__ out,
                                               const float* __restrict__ rs) {
    gemm_core<384, 1>(g_act_h, g_w2h, 0, nullptr, out, rs);
}

// ---------------- Kernel 4: depthwise 3x3 + exact GELU (half in/out) ---------
// (R14 shape: grid 1024, block (96,4), 32 cols/thread)
__global__ void k_dw(const float* __restrict__ w_dw) {
    int bi = blockIdx.x;
    int i  = bi & 127;
    int ch = threadIdx.x * 4;
    int jb = threadIdx.y * 32;

    float w[3][3][4];
    #pragma unroll
    for (int r = 0; r < 3; r++)
        #pragma unroll
        for (int cc = 0; cc < 3; cc++)
            #pragma unroll
            for (int q = 0; q < 4; q++)
                w[r][cc][q] = w_dw[(ch+q)*9 + r*3 + cc];

    const __half* r1 = g_hid_h + (size_t)bi*49152 + ch;
    const __half* r0 = r1 - 49152;
    const __half* r2 = r1 + 49152;
    const bool up = (i > 0), dn = (i < 127);

    float L[3][4], M[3][4], R[3][4];

#define DW_CVT(dst, u) do {                                                   \
    __half2 _h0 = *(__half2*)&(u).x, _h1 = *(__half2*)&(u).y;                 \
    float2 _f0 = __half22float2(_h0), _f1 = __half22float2(_h1);              \
    dst[0] = _f0.x; dst[1] = _f0.y; dst[2] = _f1.x; dst[3] = _f1.y;           \
} while (0)

#define DW_LOADCOL(dst, jj) do {                                              \
    if ((jj) >= 0 && (jj) < 128) {                                            \
        uint2 _zz = make_uint2(0, 0);                                         \
        uint2 _ua = up ? *(const uint2*)(r0 + (size_t)(jj)*384) : _zz;        \
        uint2 _ub = *(const uint2*)(r1 + (size_t)(jj)*384);                   \
        uint2 _uc = dn ? *(const uint2*)(r2 + (size_t)(jj)*384) : _zz;        \
        DW_CVT(dst[0], _ua); DW_CVT(dst[1], _ub); DW_CVT(dst[2], _uc);        \
    } else {                                                                  \
        _Pragma("unroll") for (int _r = 0; _r < 3; _r++)                      \
            _Pragma("unroll") for (int _q = 0; _q < 4; _q++) dst[_r][_q] = 0.f; \
    } } while (0)

    DW_LOADCOL(L, jb-1);
    DW_LOADCOL(M, jb);

    __half* obase = g_act_h + (size_t)bi*128*384 + ch;
    for (int j = jb; j < jb + 32; j++) {
        DW_LOADCOL(R, j+1);
        float s[4];
        #pragma unroll
        for (int q = 0; q < 4; q++) {
            float v = L[0][q]*w[0][0][q] + M[0][q]*w[0][1][q] + R[0][q]*w[0][2][q]
                    + L[1][q]*w[1][0][q] + M[1][q]*w[1][1][q] + R[1][q]*w[1][2][q]
                    + L[2][q]*w[2][0][q] + M[2][q]*w[2][1][q] + R[2][q]*w[2][2][q];
            s[q] = 0.5f * v * (1.f + erff(v * 0.70710678118654752f));
        }
        __half2 h0 = __floats2half2_rn(s[0], s[1]);
        __half2 h1 = __floats2half2_rn(s[2], s[3]);
        uint2 u;
        u.x = *(uint32_t*)&h0;
        u.y = *(uint32_t*)&h1;
        *(uint2*)(obase + (size_t)j*384) = u;
        #pragma unroll
        for (int r = 0; r < 3; r++)
            #pragma unroll
            for (int q = 0; q < 4; q++) { L[r][q] = M[r][q]; M[r][q] = R[r][q]; }
    }
#undef DW_LOADCOL
#undef DW_CVT
}

// ---------------- launch ------------------------------------------------------
extern "C" void kernel_launch(void* const* d_in, const int* in_sizes, int n_in,
                              void* d_out, int out_size) {
    const float* x     = (const float*)d_in[0];
    const float* gamma = (const float*)d_in[1];
    const float* beta  = (const float*)d_in[2];
    const float* w_in  = (const float*)d_in[3];
    const float* w_dw  = (const float*)d_in[4];
    const float* w_out = (const float*)d_in[5];
    const float* rs    = (const float*)d_in[6];
    float* out = (float*)d_out;

    const int SMG = 3 * (128*12 + 192*12) * 4;   // 46080 B (< 48K default)

    k_dwt   <<<1024, 256>>>(x, out);
    k_bnfin1<<<64,   384>>>();
    k_bnfin2<<<1,    384>>>(gamma, beta);
    k_wprep <<<768,  192>>>(w_in, w_out);
    k_gemm1 <<<dim3(2, 1024), 512, SMG>>>();
    k_dw    <<<1024, dim3(96, 4)>>>(w_dw);
    k_gemm2 <<<dim3(1, 1024), 512, SMG>>>(out, rs);
}